// round 16
// baseline (speedup 1.0000x reference)
#include <cuda_runtime.h>
#include <math_constants.h>

#define H_IN   256
#define W_IN   256
#define H_OUT  128
#define W_OUT  128
#define NEG_INF (-CUDART_INF_F)

// One lane owns 8 input cols: a = cols 8l..8l+3, b = cols 8l+4..8l+7.
// A warp spans the full 256-col row -> shuffle edges are true image borders.
struct Row8 { float4 a, b; };

// Unguarded load: row statically known in range. Pure LDG.
__device__ __forceinline__ Row8 ldrow_nc(const float* __restrict__ fp, int r, int c)
{
    Row8 x;
    const float* rp = fp + r * W_IN + c;
    x.a = __ldcs((const float4*)(rp));
    x.b = __ldcs((const float4*)(rp + 4));
    return x;
}

__device__ __forceinline__ Row8 row_ninf()
{
    Row8 x;
    x.a = make_float4(NEG_INF, NEG_INF, NEG_INF, NEG_INF);
    x.b = x.a;
    return x;
}

// Horizontal 7-tap max-plus: 4 output cols (centers 8l, 8l+2, 8l+4, 8l+6).
// Symmetric weights h[o] = -o^2/(4t): pair-max then single add.
__device__ __forceinline__ float4 hmax(const Row8& x, int lane,
                                       float h1, float h2, float h3)
{
    float m3 = __shfl_up_sync(0xffffffffu, x.b.y, 1);   // col 8l-3
    float m2 = __shfl_up_sync(0xffffffffu, x.b.z, 1);   // col 8l-2
    float m1 = __shfl_up_sync(0xffffffffu, x.b.w, 1);   // col 8l-1
    float p8 = __shfl_down_sync(0xffffffffu, x.a.x, 1); // col 8l+8
    float p9 = __shfl_down_sync(0xffffffffu, x.a.y, 1); // col 8l+9
    if (lane == 0)  { m3 = NEG_INF; m2 = NEG_INF; m1 = NEG_INF; }
    if (lane == 31) { p8 = NEG_INF; p9 = NEG_INF; }

    float4 g;
    g.x = fmaxf(fmaxf(x.a.x,                    fmaxf(m1,    x.a.y) + h1),
                fmaxf(fmaxf(m2,    x.a.z) + h2, fmaxf(m3,    x.a.w) + h3));
    g.y = fmaxf(fmaxf(x.a.z,                    fmaxf(x.a.y, x.a.w) + h1),
                fmaxf(fmaxf(x.a.x, x.b.x) + h2, fmaxf(m1,    x.b.y) + h3));
    g.z = fmaxf(fmaxf(x.b.x,                    fmaxf(x.a.w, x.b.y) + h1),
                fmaxf(fmaxf(x.a.z, x.b.z) + h2, fmaxf(x.a.y, x.b.w) + h3));
    g.w = fmaxf(fmaxf(x.b.z,                    fmaxf(x.b.y, x.b.w) + h1),
                fmaxf(fmaxf(x.b.x, p8)    + h2, fmaxf(x.a.w, p9)    + h3));
    return g;
}

__device__ __forceinline__ float4 vmax(const float4* ring, int s0,
                                       float h1, float h2, float h3)
{
    float4 c  = ring[s0 & 7];
    float4 a1 = ring[(s0 + 7) & 7], b1 = ring[(s0 + 1) & 7];
    float4 a2 = ring[(s0 + 6) & 7], b2 = ring[(s0 + 2) & 7];
    float4 a3 = ring[(s0 + 5) & 7], b3 = ring[(s0 + 3) & 7];
    float4 o;
    o.x = fmaxf(fmaxf(c.x, fmaxf(a1.x, b1.x) + h1),
                fmaxf(fmaxf(a2.x, b2.x) + h2, fmaxf(a3.x, b3.x) + h3));
    o.y = fmaxf(fmaxf(c.y, fmaxf(a1.y, b1.y) + h1),
                fmaxf(fmaxf(a2.y, b2.y) + h2, fmaxf(a3.y, b3.y) + h3));
    o.z = fmaxf(fmaxf(c.z, fmaxf(a1.z, b1.z) + h1),
                fmaxf(fmaxf(a2.z, b2.z) + h2, fmaxf(a3.z, b3.z) + h3));
    o.w = fmaxf(fmaxf(c.w, fmaxf(a1.w, b1.w) + h1),
                fmaxf(fmaxf(a2.w, b2.w) + h2, fmaxf(a3.w, b3.w) + h3));
    return o;
}

__global__ __launch_bounds__(128)
void parabolic_pool_kernel(const float* __restrict__ f,
                           const float* __restrict__ tptr,
                           float* __restrict__ out)
{
    // one warp per (plane, 64-row strip); warp spans the full 256-col width
    const int gw    = blockIdx.x * 4 + (threadIdx.x >> 5);   // 0..4095
    const int lane  = threadIdx.x & 31;
    const int plane = gw >> 1;
    const bool top  = (gw & 1) == 0;             // strip 0 (rows 0..63) ?
    const int i0    = top ? 0 : 64;              // output row strip origin
    const int cb    = 8 * lane;                  // lane's input col base

    const float* __restrict__ fp = f + (size_t)plane * (H_IN * W_IN);
    float* __restrict__ op = out + (size_t)plane * (H_OUT * W_OUT)
                                 + (size_t)i0 * W_OUT + 4 * lane;

    const float inv4t = 0.25f / tptr[0];
    const float h1 = -1.0f * inv4t;
    const float h2 = -4.0f * inv4t;
    const float h3 = -9.0f * inv4t;

    // ring[R & 7] = horizontal max-plus of input row R (local row index)
    float4 ring[8];

    // ---- prologue: input rows 2*i0-3 .. 2*i0+3, specialized per strip ----
    if (top) {
        // rows -3..-1 are OOB -> -inf without loads; rows 0..3 unguarded
        Row8 ninf = row_ninf();
        float4 gn = hmax(ninf, lane, h1, h2, h3);
        ring[5] = gn; ring[6] = gn; ring[7] = gn;
#pragma unroll
        for (int k = 0; k < 4; ++k) {
            Row8 x = ldrow_nc(fp, k, cb);
            ring[k] = hmax(x, lane, h1, h2, h3);
        }
    } else {
        // rows 125..131: all in range, unguarded
#pragma unroll
        for (int k = 0; k < 7; ++k) {
            Row8 x = ldrow_nc(fp, 125 + k, cb);
            ring[(k + 5) & 7] = hmax(x, lane, h1, h2, h3);
        }
    }

    // 2-row prefetch: rows 2*i0+4, 2*i0+5 (always in range)
    Row8 pva = ldrow_nc(fp, 2 * i0 + 4, cb);
    Row8 pvb = ldrow_nc(fp, 2 * i0 + 5, cb);

    // ---- main body: output rows 0..59; all loads statically in range ----
    // (max row loaded: 2*(i0+59)+7 = 253 < 256 for both strips)
    for (int ib = 0; ib < 15; ++ib) {
#pragma unroll
        for (int ip = 0; ip < 4; ++ip) {
            const int i = ib * 4 + ip;                  // local output row

            float4 o = vmax(ring, 2 * ip, h1, h2, h3);
            __stcs((float4*)(op + i * W_OUT), o);

            Row8 na = pva, nb = pvb;
            const int rn = 2 * (i0 + i) + 6;
            pva = ldrow_nc(fp, rn,     cb);             // unguarded
            pvb = ldrow_nc(fp, rn + 1, cb);

            ring[(2 * ip + 4) & 7] = hmax(na, lane, h1, h2, h3);
            ring[(2 * ip + 5) & 7] = hmax(nb, lane, h1, h2, h3);
        }
    }

    // ---- tail: rows 60..63; load only what is consumed ----
    // i = 60: rows 2*i0+126/127 (in range for both strips)
    {
        float4 o = vmax(ring, 0, h1, h2, h3);
        __stcs((float4*)(op + 60 * W_OUT), o);
        Row8 na = pva, nb = pvb;
        pva = ldrow_nc(fp, 2 * i0 + 126, cb);
        pvb = ldrow_nc(fp, 2 * i0 + 127, cb);
        ring[4] = hmax(na, lane, h1, h2, h3);
        ring[5] = hmax(nb, lane, h1, h2, h3);
    }
    // i = 61: rows 2*i0+128/129 -- in range for top strip, OOB for bottom
    {
        float4 o = vmax(ring, 2, h1, h2, h3);
        __stcs((float4*)(op + 61 * W_OUT), o);
        Row8 na = pva, nb = pvb;
        if (top) {
            pva = ldrow_nc(fp, 128, cb);
            pvb = ldrow_nc(fp, 129, cb);
        } else {
            pva = row_ninf();
            pvb = row_ninf();
        }
        ring[6] = hmax(na, lane, h1, h2, h3);
        ring[7] = hmax(nb, lane, h1, h2, h3);
    }
    // i = 62: no loads (rows 130+ never consumed)
    {
        float4 o = vmax(ring, 4, h1, h2, h3);
        __stcs((float4*)(op + 62 * W_OUT), o);
        ring[0] = hmax(pva, lane, h1, h2, h3);
        ring[1] = hmax(pvb, lane, h1, h2, h3);
    }
    // i = 63: consume only
    {
        float4 o = vmax(ring, 6, h1, h2, h3);
        __stcs((float4*)(op + 63 * W_OUT), o);
    }
}

extern "C" void kernel_launch(void* const* d_in, const int* in_sizes, int n_in,
                              void* d_out, int out_size)
{
    const float* f = (const float*)d_in[0];
    const float* t = (const float*)d_in[1];
    float* out = (float*)d_out;

    // 2048 planes x 2 row-strips = 4096 warps = 1024 blocks x 4 warps
    parabolic_pool_kernel<<<1024, 128>>>(f, t, out);
}

// round 17
// speedup vs baseline: 1.2345x; 1.2345x over previous
#include <cuda_runtime.h>
#include <math_constants.h>

#define H_IN   256
#define W_IN   256
#define H_OUT  128
#define W_OUT  128
#define NEG_INF (-CUDART_INF_F)

// One lane owns 8 input cols: a = cols 8l..8l+3, b = cols 8l+4..8l+7.
// A warp spans the full 256-col row -> shuffle edges are true image borders.
struct Row8 { float4 a, b; };

// Guarded load (prologue / bottom edge only): OOB rows -> -inf.
__device__ __forceinline__ Row8 ldrow(const float* __restrict__ fp, int r, int c)
{
    Row8 x;
    x.a = make_float4(NEG_INF, NEG_INF, NEG_INF, NEG_INF);
    x.b = x.a;
    if ((unsigned)r < (unsigned)H_IN) {
        const float* rp = fp + r * W_IN + c;
        x.a = __ldcs((const float4*)(rp));
        x.b = __ldcs((const float4*)(rp + 4));
    }
    return x;
}

// Unguarded load for the main body: row is statically known in range.
// No -inf init, no compare -- pure LDG with immediate offsets.
__device__ __forceinline__ Row8 ldrow_nc(const float* __restrict__ fp, int r, int c)
{
    Row8 x;
    const float* rp = fp + r * W_IN + c;
    x.a = __ldcs((const float4*)(rp));
    x.b = __ldcs((const float4*)(rp + 4));
    return x;
}

// Horizontal 7-tap max-plus: 4 output cols (centers 8l, 8l+2, 8l+4, 8l+6).
// Symmetric weights h[o] = -o^2/(4t): pair-max then single add.
__device__ __forceinline__ float4 hmax(const Row8& x, int lane,
                                       float h1, float h2, float h3)
{
    float m3 = __shfl_up_sync(0xffffffffu, x.b.y, 1);   // col 8l-3
    float m2 = __shfl_up_sync(0xffffffffu, x.b.z, 1);   // col 8l-2
    float m1 = __shfl_up_sync(0xffffffffu, x.b.w, 1);   // col 8l-1
    float p8 = __shfl_down_sync(0xffffffffu, x.a.x, 1); // col 8l+8
    float p9 = __shfl_down_sync(0xffffffffu, x.a.y, 1); // col 8l+9
    if (lane == 0)  { m3 = NEG_INF; m2 = NEG_INF; m1 = NEG_INF; }
    if (lane == 31) { p8 = NEG_INF; p9 = NEG_INF; }

    float4 g;
    g.x = fmaxf(fmaxf(x.a.x,                    fmaxf(m1,    x.a.y) + h1),
                fmaxf(fmaxf(m2,    x.a.z) + h2, fmaxf(m3,    x.a.w) + h3));
    g.y = fmaxf(fmaxf(x.a.z,                    fmaxf(x.a.y, x.a.w) + h1),
                fmaxf(fmaxf(x.a.x, x.b.x) + h2, fmaxf(m1,    x.b.y) + h3));
    g.z = fmaxf(fmaxf(x.b.x,                    fmaxf(x.a.w, x.b.y) + h1),
                fmaxf(fmaxf(x.a.z, x.b.z) + h2, fmaxf(x.a.y, x.b.w) + h3));
    g.w = fmaxf(fmaxf(x.b.z,                    fmaxf(x.b.y, x.b.w) + h1),
                fmaxf(fmaxf(x.b.x, p8)    + h2, fmaxf(x.a.w, p9)    + h3));
    return g;
}

__device__ __forceinline__ float4 vmax(const float4* ring, int s0,
                                       float h1, float h2, float h3)
{
    float4 c  = ring[s0 & 7];
    float4 a1 = ring[(s0 + 7) & 7], b1 = ring[(s0 + 1) & 7];
    float4 a2 = ring[(s0 + 6) & 7], b2 = ring[(s0 + 2) & 7];
    float4 a3 = ring[(s0 + 5) & 7], b3 = ring[(s0 + 3) & 7];
    float4 o;
    o.x = fmaxf(fmaxf(c.x, fmaxf(a1.x, b1.x) + h1),
                fmaxf(fmaxf(a2.x, b2.x) + h2, fmaxf(a3.x, b3.x) + h3));
    o.y = fmaxf(fmaxf(c.y, fmaxf(a1.y, b1.y) + h1),
                fmaxf(fmaxf(a2.y, b2.y) + h2, fmaxf(a3.y, b3.y) + h3));
    o.z = fmaxf(fmaxf(c.z, fmaxf(a1.z, b1.z) + h1),
                fmaxf(fmaxf(a2.z, b2.z) + h2, fmaxf(a3.z, b3.z) + h3));
    o.w = fmaxf(fmaxf(c.w, fmaxf(a1.w, b1.w) + h1),
                fmaxf(fmaxf(a2.w, b2.w) + h2, fmaxf(a3.w, b3.w) + h3));
    return o;
}

__global__ __launch_bounds__(128)
void parabolic_pool_kernel(const float* __restrict__ f,
                           const float* __restrict__ tptr,
                           float* __restrict__ out)
{
    // one warp per (plane, 64-row strip); warp spans the full 256-col width
    const int gw    = blockIdx.x * 4 + (threadIdx.x >> 5);   // 0..4095
    const int lane  = threadIdx.x & 31;
    const int plane = gw >> 1;
    const int i0    = (gw & 1) * 64;             // output row strip origin
    const int cb    = 8 * lane;                  // lane's input col base

    const float* __restrict__ fp = f + (size_t)plane * (H_IN * W_IN);
    float* __restrict__ op = out + (size_t)plane * (H_OUT * W_OUT)
                                 + (size_t)i0 * W_OUT + 4 * lane;

    const float inv4t = 0.25f / tptr[0];
    const float h1 = -1.0f * inv4t;
    const float h2 = -4.0f * inv4t;
    const float h3 = -9.0f * inv4t;

    // ring[R & 7] = horizontal max-plus of input row R (local row index)
    float4 ring[8];

    // ---- prologue: input rows 2*i0-3 .. 2*i0+3 (guarded: top edge) ----
#pragma unroll
    for (int k = 0; k < 7; ++k) {
        Row8 x = ldrow(fp, 2 * i0 - 3 + k, cb);
        ring[(k + 5) & 7] = hmax(x, lane, h1, h2, h3);
    }

    // 2-row prefetch: rows 2*i0+4, 2*i0+5 (always in range)
    Row8 pva = ldrow_nc(fp, 2 * i0 + 4, cb);
    Row8 pvb = ldrow_nc(fp, 2 * i0 + 5, cb);

    // ---- main body: output rows 0..59; all loads statically in range ----
    // (max row loaded: 2*(i0+59)+7 = 253 < 256 for both strips)
    for (int ib = 0; ib < 15; ++ib) {
#pragma unroll
        for (int ip = 0; ip < 4; ++ip) {
            const int i = ib * 4 + ip;                  // local output row

            float4 o = vmax(ring, 2 * ip, h1, h2, h3);
            __stcs((float4*)(op + i * W_OUT), o);

            Row8 na = pva, nb = pvb;
            const int rn = 2 * (i0 + i) + 6;
            pva = ldrow_nc(fp, rn,     cb);             // unguarded
            pvb = ldrow_nc(fp, rn + 1, cb);

            ring[(2 * ip + 4) & 7] = hmax(na, lane, h1, h2, h3);
            ring[(2 * ip + 5) & 7] = hmax(nb, lane, h1, h2, h3);
        }
    }

    // ---- tail: rows 60..63; load only what is consumed ----
    // i = 60: load rows 2*i0+126/127 (in range for both strips)
    {
        float4 o = vmax(ring, 0, h1, h2, h3);
        __stcs((float4*)(op + 60 * W_OUT), o);
        Row8 na = pva, nb = pvb;
        pva = ldrow_nc(fp, 2 * i0 + 126, cb);
        pvb = ldrow_nc(fp, 2 * i0 + 127, cb);
        ring[4] = hmax(na, lane, h1, h2, h3);
        ring[5] = hmax(nb, lane, h1, h2, h3);
    }
    // i = 61: load rows 2*i0+128/129 (guarded: OOB for the upper strip)
    {
        float4 o = vmax(ring, 2, h1, h2, h3);
        __stcs((float4*)(op + 61 * W_OUT), o);
        Row8 na = pva, nb = pvb;
        pva = ldrow(fp, 2 * i0 + 128, cb);
        pvb = ldrow(fp, 2 * i0 + 129, cb);
        ring[6] = hmax(na, lane, h1, h2, h3);
        ring[7] = hmax(nb, lane, h1, h2, h3);
    }
    // i = 62: no loads (rows 130+ never consumed)
    {
        float4 o = vmax(ring, 4, h1, h2, h3);
        __stcs((float4*)(op + 62 * W_OUT), o);
        ring[0] = hmax(pva, lane, h1, h2, h3);
        ring[1] = hmax(pvb, lane, h1, h2, h3);
    }
    // i = 63: consume only
    {
        float4 o = vmax(ring, 6, h1, h2, h3);
        __stcs((float4*)(op + 63 * W_OUT), o);
    }
}

extern "C" void kernel_launch(void* const* d_in, const int* in_sizes, int n_in,
                              void* d_out, int out_size)
{
    const float* f = (const float*)d_in[0];
    const float* t = (const float*)d_in[1];
    float* out = (float*)d_out;

    // 2048 planes x 2 row-strips = 4096 warps = 1024 blocks x 4 warps
    parabolic_pool_kernel<<<1024, 128>>>(f, t, out);
}